// round 5
// baseline (speedup 1.0000x reference)
#include <cuda_runtime.h>

#define NVOX 2097152u            // 128^3
#define PLANE 16384              // 128*128

// Scratch: ssd[t][n][c][z][y][x]  (2*2*12*128^3 floats = 402 MB)
__device__ float g_ssd[(size_t)2 * 2 * 12 * NVOX];
__device__ float g_msum[2];
__device__ float g_loss;

__global__ void zero_kernel() {
    if (threadIdx.x == 0) { g_msum[0] = 0.f; g_msum[1] = 0.f; g_loss = 0.f; }
}

struct Acc { float4 a, b, c; };

__device__ __forceinline__ void f4zero(Acc& A) {
    A.a = make_float4(0.f,0.f,0.f,0.f);
    A.b = make_float4(0.f,0.f,0.f,0.f);
    A.c = make_float4(0.f,0.f,0.f,0.f);
}
__device__ __forceinline__ float4 f4add3(float4 p, float4 q, float4 r) {
    return make_float4(p.x+q.x+r.x, p.y+q.y+r.y, p.z+q.z+r.z, p.w+q.w+r.w);
}
__device__ __forceinline__ void f4acc(Acc& A, float4 s0, float4 s1, float4 s2) {
    A.a.x += s0.x; A.a.y += s0.y; A.a.z += s0.z; A.a.w += s0.w;
    A.b.x += s1.x; A.b.y += s1.y; A.b.z += s1.z; A.b.w += s1.w;
    A.c.x += s2.x; A.c.y += s2.y; A.c.z += s2.z; A.c.w += s2.w;
}

__device__ __forceinline__ void finalize(int zo, const Acc& A,
                                         float* __restrict__ outBase, float& mvsum)
{
    const float k = 1.f / 27.f;
    float v0  = A.a.x*k, v1  = A.a.y*k, v2  = A.a.z*k, v3  = A.a.w*k;
    float v4  = A.b.x*k, v5  = A.b.y*k, v6  = A.b.z*k, v7  = A.b.w*k;
    float v8  = A.c.x*k, v9  = A.c.y*k, v10 = A.c.z*k, v11 = A.c.w*k;
    float* o = outBase + (size_t)zo * PLANE;
    o[(size_t)0*NVOX]  = v0;  o[(size_t)1*NVOX]  = v1;
    o[(size_t)2*NVOX]  = v2;  o[(size_t)3*NVOX]  = v3;
    o[(size_t)4*NVOX]  = v4;  o[(size_t)5*NVOX]  = v5;
    o[(size_t)6*NVOX]  = v6;  o[(size_t)7*NVOX]  = v7;
    o[(size_t)8*NVOX]  = v8;  o[(size_t)9*NVOX]  = v9;
    o[(size_t)10*NVOX] = v10; o[(size_t)11*NVOX] = v11;
    float mn = fminf(fminf(fminf(v0,v1),fminf(v2,v3)),
                     fminf(fminf(fminf(v4,v5),fminf(v6,v7)),
                           fminf(fminf(v8,v9),fminf(v10,v11))));
    float sm = ((v0+v1)+(v2+v3)) + ((v4+v5)+(v6+v7)) + ((v8+v9)+(v10+v11));
    mvsum += sm * (1.f/12.f) - mn;
}

__device__ __forceinline__ void step(
    int zp, Acc& AP, Acc& AC, Acc& AN,
    const float* __restrict__ img,
    float (*simg)[8][128], float4 (*ysb)[128][3],
    int y0, int lin, int x, int ty,
    int xm2, int xp2, int xm1, int xp1, int gy0,
    float* __restrict__ outBase, float& mvsum)
{
    if (zp >= 128) return;

    f4zero(AN);

    // stage img plane zp+2 (z edge-clamped)
    {
        const int slot = (zp + 2) % 5;
        const float* src = img + (size_t)min(zp + 2, 127) * PLANE;
        for (int e = lin; e < 1024; e += 256) {
            int row = e >> 7, xx = e & 127;
            int gy = min(max(y0 - 3 + row, 0), 127);
            simg[slot][row][xx] = src[gy * 128 + xx];
        }
    }
    __syncthreads();

    // y-summed diff2 for 12 channels, directly from 6 samples per dy
    const float* Pzm = &simg[(zp + 3) % 5][0][0];   // plane zp-2 (clamped)
    const float* Pzc = &simg[ zp      % 5][0][0];   // plane zp
    const float* Pzp = &simg[(zp + 2) % 5][0][0];   // plane zp+2 (clamped)

    float ys[12];
    #pragma unroll
    for (int c = 0; c < 12; ++c) ys[c] = 0.f;

    #pragma unroll
    for (int dy = -1; dy <= 1; ++dy) {
        int ly = min(max(gy0 + dy, 0), 127);
        int r  = (ly - y0 + 3) * 128;
        int rm = (max(ly - 2, 0)   - y0 + 3) * 128;
        int rp = (min(ly + 2, 127) - y0 + 3) * 128;
        float V0 = Pzm[r  + x];      // z-2
        float V1 = Pzc[r  + xm2];    // x-2
        float V2 = Pzc[rm + x];      // y-2
        float V3 = Pzc[r  + xp2];    // x+2
        float V4 = Pzp[r  + x];      // z+2
        float V5 = Pzc[rp + x];      // y+2
        float d;
        d = V1 - V0; ys[0]  += d*d;
        d = V2 - V0; ys[1]  += d*d;
        d = V2 - V1; ys[2]  += d*d;
        d = V3 - V0; ys[3]  += d*d;
        d = V3 - V2; ys[4]  += d*d;
        d = V4 - V1; ys[5]  += d*d;
        d = V4 - V2; ys[6]  += d*d;
        d = V4 - V3; ys[7]  += d*d;
        d = V5 - V0; ys[8]  += d*d;
        d = V5 - V1; ys[9]  += d*d;
        d = V5 - V3; ys[10] += d*d;
        d = V5 - V4; ys[11] += d*d;
    }
    ysb[ty][x][0] = make_float4(ys[0], ys[1], ys[2],  ys[3]);
    ysb[ty][x][1] = make_float4(ys[4], ys[5], ys[6],  ys[7]);
    ysb[ty][x][2] = make_float4(ys[8], ys[9], ys[10], ys[11]);
    __syncthreads();

    // x-sum (x edge-clamped)
    float4 s0 = f4add3(ysb[ty][xm1][0], ysb[ty][x][0], ysb[ty][xp1][0]);
    float4 s1 = f4add3(ysb[ty][xm1][1], ysb[ty][x][1], ysb[ty][xp1][1]);
    float4 s2 = f4add3(ysb[ty][xm1][2], ysb[ty][x][2], ysb[ty][xp1][2]);

    // z accumulation into zo = zp-1, zp, zp+1
    f4acc(AP, s0, s1, s2);
    f4acc(AC, s0, s1, s2);
    f4acc(AN, s0, s1, s2);
    if (zp == 0)   f4acc(AC, s0, s1, s2);   // virtual plane -1  -> zo=0
    if (zp == 127) f4acc(AC, s0, s1, s2);   // virtual plane 128 -> zo=127

    if (zp >= 1)   finalize(zp - 1, AP, outBase, mvsum);
    if (zp == 127) finalize(127,    AC, outBase, mvsum);
}

__global__ __launch_bounds__(256)
void ssd_kernel(const float* __restrict__ pred, const float* __restrict__ targ)
{
    const int x  = threadIdx.x;
    const int ty = threadIdx.y;
    const int y0 = blockIdx.x * 2;
    const int n  = blockIdx.y;
    const int t  = blockIdx.z;

    const float* img = (t == 0 ? pred : targ) + (size_t)n * NVOX;
    float* outBase = g_ssd + (size_t)(t * 2 + n) * 12u * NVOX
                   + (size_t)(y0 + ty) * 128 + x;

    __shared__ float  simg[5][8][128];
    __shared__ float4 ysb[2][128][3];
    __shared__ float  red[256];

    const int lin = ty * 128 + x;

    // preload planes q = -2..1 (z edge-clamped)
    for (int q = -2; q <= 1; ++q) {
        const int slot = (q + 10) % 5;
        const float* src = img + (size_t)max(q, 0) * PLANE;
        for (int e = lin; e < 1024; e += 256) {
            int row = e >> 7, xx = e & 127;
            int gy = min(max(y0 - 3 + row, 0), 127);
            simg[slot][row][xx] = src[gy * 128 + xx];
        }
    }

    const int xm2 = max(x - 2, 0), xp2 = min(x + 2, 127);
    const int xm1 = max(x - 1, 0), xp1 = min(x + 1, 127);
    const int gy0 = y0 + ty;

    Acc A0, A1, A2;            // acc for zo ≡ 0,1,2 (mod 3)
    f4zero(A0); f4zero(A1); f4zero(A2);
    float mvsum = 0.f;

    for (int zb = 0; zb < 129; zb += 3) {
        step(zb + 0, A2, A0, A1, img, simg, ysb, y0, lin, x, ty,
             xm2, xp2, xm1, xp1, gy0, outBase, mvsum);
        step(zb + 1, A0, A1, A2, img, simg, ysb, y0, lin, x, ty,
             xm2, xp2, xm1, xp1, gy0, outBase, mvsum);
        step(zb + 2, A1, A2, A0, img, simg, ysb, y0, lin, x, ty,
             xm2, xp2, xm1, xp1, gy0, outBase, mvsum);
    }

    // block-reduce mind_var partial sum
    red[lin] = mvsum;
    __syncthreads();
    for (int off = 128; off > 0; off >>= 1) {
        if (lin < off) red[lin] += red[lin + off];
        __syncthreads();
    }
    if (lin == 0) atomicAdd(&g_msum[t], red[0]);
}

__global__ __launch_bounds__(256)
void loss_kernel()
{
    const unsigned i = blockIdx.x * 256u + threadIdx.x;   // 0 .. 2*128^3-1
    const float mP = g_msum[0] * (1.f / 4194304.f);
    const float mT = g_msum[1] * (1.f / 4194304.f);

    const unsigned nn = i >> 21;
    const unsigned s  = i & (NVOX - 1);

    const float* bp = g_ssd + (size_t)nn       * 12u * NVOX + s;
    const float* bt = g_ssd + (size_t)(2 + nn) * 12u * NVOX + s;

    float vp[12], vt[12];
    #pragma unroll
    for (int c = 0; c < 12; ++c) vp[c] = bp[(size_t)c * NVOX];
    #pragma unroll
    for (int c = 0; c < 12; ++c) vt[c] = bt[(size_t)c * NVOX];

    float mnp = vp[0], smp = vp[0];
    float mnt = vt[0], smt = vt[0];
    #pragma unroll
    for (int c = 1; c < 12; ++c) {
        mnp = fminf(mnp, vp[c]); smp += vp[c];
        mnt = fminf(mnt, vt[c]); smt += vt[c];
    }
    float mvp = smp * (1.f/12.f) - mnp;
    float mvt = smt * (1.f/12.f) - mnt;
    mvp = fminf(fmaxf(mvp, 0.001f * mP), 1000.f * mP);
    mvt = fminf(fmaxf(mvt, 0.001f * mT), 1000.f * mT);
    const float ivp = 1.f / mvp;
    const float ivt = 1.f / mvt;

    float acc = 0.f;
    #pragma unroll
    for (int c = 0; c < 12; ++c) {
        float ep = __expf(-(vp[c] - mnp) * ivp);
        float et = __expf(-(vt[c] - mnt) * ivt);
        float d = ep - et;
        acc += d * d;
    }

    __shared__ float red[256];
    red[threadIdx.x] = acc;
    __syncthreads();
    for (int off = 128; off > 0; off >>= 1) {
        if (threadIdx.x < off) red[threadIdx.x] += red[threadIdx.x + off];
        __syncthreads();
    }
    if (threadIdx.x == 0) atomicAdd(&g_loss, red[0]);
}

__global__ void finish_kernel(float* __restrict__ out)
{
    out[0] = g_loss * (1.f / 50331648.f);
}

extern "C" void kernel_launch(void* const* d_in, const int* in_sizes, int n_in,
                              void* d_out, int out_size)
{
    const float* pred = (const float*)d_in[0];
    const float* targ = (const float*)d_in[1];

    zero_kernel<<<1, 32>>>();
    ssd_kernel<<<dim3(64, 2, 2), dim3(128, 2)>>>(pred, targ);
    loss_kernel<<<16384, 256>>>();
    finish_kernel<<<1, 1>>>((float*)d_out);
}

// round 6
// speedup vs baseline: 1.6966x; 1.6966x over previous
#include <cuda_runtime.h>

#define NVOX 2097152u            // 128^3
#define PLANE 16384              // 128*128
#define CH 32                    // output z-planes per block (z-chunking)

// Scratch: ssd[t][n][c][z][y][x]  (2*2*12*128^3 floats = 402 MB)
__device__ float g_ssd[(size_t)2 * 2 * 12 * NVOX];
__device__ float g_msum[2];
__device__ float g_loss;

__global__ void zero_kernel() {
    if (threadIdx.x == 0) { g_msum[0] = 0.f; g_msum[1] = 0.f; g_loss = 0.f; }
}

struct Acc { float4 a, b, c; };

__device__ __forceinline__ void f4zero(Acc& A) {
    A.a = make_float4(0.f,0.f,0.f,0.f);
    A.b = make_float4(0.f,0.f,0.f,0.f);
    A.c = make_float4(0.f,0.f,0.f,0.f);
}
__device__ __forceinline__ float4 f4add3(float4 p, float4 q, float4 r) {
    return make_float4(p.x+q.x+r.x, p.y+q.y+r.y, p.z+q.z+r.z, p.w+q.w+r.w);
}
__device__ __forceinline__ void f4acc(Acc& A, float4 s0, float4 s1, float4 s2) {
    A.a.x += s0.x; A.a.y += s0.y; A.a.z += s0.z; A.a.w += s0.w;
    A.b.x += s1.x; A.b.y += s1.y; A.b.z += s1.z; A.b.w += s1.w;
    A.c.x += s2.x; A.c.y += s2.y; A.c.z += s2.z; A.c.w += s2.w;
}

__device__ __forceinline__ void finalize(int zo, const Acc& A,
                                         float* __restrict__ outBase, float& mvsum)
{
    const float k = 1.f / 27.f;
    float v0  = A.a.x*k, v1  = A.a.y*k, v2  = A.a.z*k, v3  = A.a.w*k;
    float v4  = A.b.x*k, v5  = A.b.y*k, v6  = A.b.z*k, v7  = A.b.w*k;
    float v8  = A.c.x*k, v9  = A.c.y*k, v10 = A.c.z*k, v11 = A.c.w*k;
    float* o = outBase + (size_t)zo * PLANE;
    o[(size_t)0*NVOX]  = v0;  o[(size_t)1*NVOX]  = v1;
    o[(size_t)2*NVOX]  = v2;  o[(size_t)3*NVOX]  = v3;
    o[(size_t)4*NVOX]  = v4;  o[(size_t)5*NVOX]  = v5;
    o[(size_t)6*NVOX]  = v6;  o[(size_t)7*NVOX]  = v7;
    o[(size_t)8*NVOX]  = v8;  o[(size_t)9*NVOX]  = v9;
    o[(size_t)10*NVOX] = v10; o[(size_t)11*NVOX] = v11;
    float mn = fminf(fminf(fminf(v0,v1),fminf(v2,v3)),
                     fminf(fminf(fminf(v4,v5),fminf(v6,v7)),
                           fminf(fminf(v8,v9),fminf(v10,v11))));
    float sm = ((v0+v1)+(v2+v3)) + ((v4+v5)+(v6+v7)) + ((v8+v9)+(v10+v11));
    mvsum += sm * (1.f/12.f) - mn;
}

__device__ __forceinline__ void stepC(
    int zp, int zlo, int zhi, int fz0, int fz1,
    Acc& AP, Acc& AC, Acc& AN,
    const float* __restrict__ img,
    float (*simg)[8][128], float4 (*ysb)[128][3],
    float pf[4],
    int y0, int lin, int x, int ty,
    int xm2, int xp2, int xm1, int xp1, int gy0,
    float* __restrict__ outBase, float& mvsum)
{
    if (zp < zlo || zp > zhi) return;   // uniform per-block guard

    f4zero(AN);

    // STS plane zp+2 (prefetched into pf at previous step / preload)
    {
        const int slot = (zp + 2) % 5;
        #pragma unroll
        for (int k = 0; k < 4; ++k) {
            int e = lin + k * 256;
            int row = e >> 7, xx = e & 127;
            simg[slot][row][xx] = pf[k];
        }
    }
    // issue prefetch for plane zp+3 (clamped); consumed next step
    {
        const float* src = img + (size_t)min(zp + 3, 127) * PLANE;
        #pragma unroll
        for (int k = 0; k < 4; ++k) {
            int e = lin + k * 256;
            int row = e >> 7, xx = e & 127;
            int gy = min(max(y0 - 3 + row, 0), 127);
            pf[k] = src[gy * 128 + xx];
        }
    }
    __syncthreads();

    // y-summed diff2 for 12 channels, directly from 6 samples per dy
    const float* Pzm = &simg[(zp + 3) % 5][0][0];   // plane zp-2 (clamped)
    const float* Pzc = &simg[ zp      % 5][0][0];   // plane zp
    const float* Pzp = &simg[(zp + 2) % 5][0][0];   // plane zp+2 (clamped)

    float ys[12];
    #pragma unroll
    for (int c = 0; c < 12; ++c) ys[c] = 0.f;

    #pragma unroll
    for (int dy = -1; dy <= 1; ++dy) {
        int ly = min(max(gy0 + dy, 0), 127);
        int r  = (ly - y0 + 3) * 128;
        int rm = (max(ly - 2, 0)   - y0 + 3) * 128;
        int rp = (min(ly + 2, 127) - y0 + 3) * 128;
        float V0 = Pzm[r  + x];      // z-2
        float V1 = Pzc[r  + xm2];    // x-2
        float V2 = Pzc[rm + x];      // y-2
        float V3 = Pzc[r  + xp2];    // x+2
        float V4 = Pzp[r  + x];      // z+2
        float V5 = Pzc[rp + x];      // y+2
        float d;
        d = V1 - V0; ys[0]  += d*d;
        d = V2 - V0; ys[1]  += d*d;
        d = V2 - V1; ys[2]  += d*d;
        d = V3 - V0; ys[3]  += d*d;
        d = V3 - V2; ys[4]  += d*d;
        d = V4 - V1; ys[5]  += d*d;
        d = V4 - V2; ys[6]  += d*d;
        d = V4 - V3; ys[7]  += d*d;
        d = V5 - V0; ys[8]  += d*d;
        d = V5 - V1; ys[9]  += d*d;
        d = V5 - V3; ys[10] += d*d;
        d = V5 - V4; ys[11] += d*d;
    }
    ysb[ty][x][0] = make_float4(ys[0], ys[1], ys[2],  ys[3]);
    ysb[ty][x][1] = make_float4(ys[4], ys[5], ys[6],  ys[7]);
    ysb[ty][x][2] = make_float4(ys[8], ys[9], ys[10], ys[11]);
    __syncthreads();

    // x-sum (x edge-clamped)
    float4 s0 = f4add3(ysb[ty][xm1][0], ysb[ty][x][0], ysb[ty][xp1][0]);
    float4 s1 = f4add3(ysb[ty][xm1][1], ysb[ty][x][1], ysb[ty][xp1][1]);
    float4 s2 = f4add3(ysb[ty][xm1][2], ysb[ty][x][2], ysb[ty][xp1][2]);

    // z accumulation into zo = zp-1, zp, zp+1
    f4acc(AP, s0, s1, s2);
    f4acc(AC, s0, s1, s2);
    f4acc(AN, s0, s1, s2);
    if (zp == 0)   f4acc(AC, s0, s1, s2);   // virtual plane -1  -> zo=0
    if (zp == 127) f4acc(AC, s0, s1, s2);   // virtual plane 128 -> zo=127

    if (zp - 1 >= fz0 && zp - 1 < fz1) finalize(zp - 1, AP, outBase, mvsum);
    if (zp == 127 && fz1 == 128)       finalize(127,    AC, outBase, mvsum);
}

__global__ __launch_bounds__(256)
void ssd_kernel(const float* __restrict__ pred, const float* __restrict__ targ)
{
    const int x  = threadIdx.x;
    const int ty = threadIdx.y;
    const int y0 = blockIdx.x * 2;
    const int zc = blockIdx.y;            // z chunk
    const int tn = blockIdx.z;            // t*2+n
    const int t  = tn >> 1;
    const int n  = tn & 1;

    const int z0 = zc * CH, z1 = z0 + CH;
    const int zlo = max(z0 - 1, 0);
    const int zhi = min(z1, 127);

    const float* img = (t == 0 ? pred : targ) + (size_t)n * NVOX;
    float* outBase = g_ssd + (size_t)tn * 12u * NVOX
                   + (size_t)(y0 + ty) * 128 + x;

    __shared__ float  simg[5][8][128];
    __shared__ float4 ysb[2][128][3];
    __shared__ float  red[256];

    const int lin = ty * 128 + x;

    // preload planes q = zlo-2 .. zlo+1 (z edge-clamped) straight into smem
    for (int q = zlo - 2; q <= zlo + 1; ++q) {
        const int slot = (q + 10) % 5;
        const float* src = img + (size_t)min(max(q, 0), 127) * PLANE;
        #pragma unroll
        for (int k = 0; k < 4; ++k) {
            int e = lin + k * 256;
            int row = e >> 7, xx = e & 127;
            int gy = min(max(y0 - 3 + row, 0), 127);
            simg[slot][row][xx] = src[gy * 128 + xx];
        }
    }
    // prefetch plane zlo+2 into registers (first step stores it)
    float pf[4];
    {
        const float* src = img + (size_t)min(zlo + 2, 127) * PLANE;
        #pragma unroll
        for (int k = 0; k < 4; ++k) {
            int e = lin + k * 256;
            int row = e >> 7, xx = e & 127;
            int gy = min(max(y0 - 3 + row, 0), 127);
            pf[k] = src[gy * 128 + xx];
        }
    }

    const int xm2 = max(x - 2, 0), xp2 = min(x + 2, 127);
    const int xm1 = max(x - 1, 0), xp1 = min(x + 1, 127);
    const int gy0 = y0 + ty;

    Acc A0, A1, A2;            // acc for zo ≡ 0,1,2 (mod 3)
    f4zero(A0); f4zero(A1); f4zero(A2);
    float mvsum = 0.f;

    const int zbase = (zlo / 3) * 3;
    for (int zb = zbase; zb <= zhi; zb += 3) {
        stepC(zb + 0, zlo, zhi, z0, z1, A2, A0, A1, img, simg, ysb, pf,
              y0, lin, x, ty, xm2, xp2, xm1, xp1, gy0, outBase, mvsum);
        stepC(zb + 1, zlo, zhi, z0, z1, A0, A1, A2, img, simg, ysb, pf,
              y0, lin, x, ty, xm2, xp2, xm1, xp1, gy0, outBase, mvsum);
        stepC(zb + 2, zlo, zhi, z0, z1, A1, A2, A0, img, simg, ysb, pf,
              y0, lin, x, ty, xm2, xp2, xm1, xp1, gy0, outBase, mvsum);
    }

    // block-reduce mind_var partial sum
    red[lin] = mvsum;
    __syncthreads();
    for (int off = 128; off > 0; off >>= 1) {
        if (lin < off) red[lin] += red[lin + off];
        __syncthreads();
    }
    if (lin == 0) atomicAdd(&g_msum[t], red[0]);
}

__global__ __launch_bounds__(256)
void loss_kernel()
{
    const unsigned i4 = blockIdx.x * 256u + threadIdx.x;   // float4 index, 0 .. 2*NVOX/4-1
    const float mP = g_msum[0] * (1.f / 4194304.f);
    const float mT = g_msum[1] * (1.f / 4194304.f);

    const unsigned nn = i4 >> 19;               // (i4*4) >> 21
    const unsigned s4 = i4 & ((NVOX / 4u) - 1u);

    const float4* bp = (const float4*)g_ssd + (size_t)nn       * 12u * (NVOX/4u) + s4;
    const float4* bt = (const float4*)g_ssd + (size_t)(2 + nn) * 12u * (NVOX/4u) + s4;

    float4 vp[12], vt[12];
    #pragma unroll
    for (int c = 0; c < 12; ++c) vp[c] = bp[(size_t)c * (NVOX/4u)];
    #pragma unroll
    for (int c = 0; c < 12; ++c) vt[c] = bt[(size_t)c * (NVOX/4u)];

    const float* fp = (const float*)vp;
    const float* ft = (const float*)vt;

    float acc = 0.f;
    #pragma unroll
    for (int comp = 0; comp < 4; ++comp) {
        float mnp = fp[comp], smp = fp[comp];
        float mnt = ft[comp], smt = ft[comp];
        #pragma unroll
        for (int c = 1; c < 12; ++c) {
            float p = fp[c * 4 + comp], q = ft[c * 4 + comp];
            mnp = fminf(mnp, p); smp += p;
            mnt = fminf(mnt, q); smt += q;
        }
        float mvp = smp * (1.f/12.f) - mnp;
        float mvt = smt * (1.f/12.f) - mnt;
        mvp = fminf(fmaxf(mvp, 0.001f * mP), 1000.f * mP);
        mvt = fminf(fmaxf(mvt, 0.001f * mT), 1000.f * mT);
        const float ivp = 1.f / mvp;
        const float ivt = 1.f / mvt;
        #pragma unroll
        for (int c = 0; c < 12; ++c) {
            float ep = __expf(-(fp[c * 4 + comp] - mnp) * ivp);
            float et = __expf(-(ft[c * 4 + comp] - mnt) * ivt);
            float d = ep - et;
            acc += d * d;
        }
    }

    __shared__ float red[256];
    red[threadIdx.x] = acc;
    __syncthreads();
    for (int off = 128; off > 0; off >>= 1) {
        if (threadIdx.x < off) red[threadIdx.x] += red[threadIdx.x + off];
        __syncthreads();
    }
    if (threadIdx.x == 0) atomicAdd(&g_loss, red[0]);
}

__global__ void finish_kernel(float* __restrict__ out)
{
    out[0] = g_loss * (1.f / 50331648.f);
}

extern "C" void kernel_launch(void* const* d_in, const int* in_sizes, int n_in,
                              void* d_out, int out_size)
{
    const float* pred = (const float*)d_in[0];
    const float* targ = (const float*)d_in[1];

    zero_kernel<<<1, 32>>>();
    ssd_kernel<<<dim3(64, 128 / CH, 4), dim3(128, 2)>>>(pred, targ);
    loss_kernel<<<4096, 256>>>();
    finish_kernel<<<1, 1>>>((float*)d_out);
}

// round 9
// speedup vs baseline: 1.7608x; 1.0378x over previous
#include <cuda_runtime.h>
#include <cuda_fp16.h>

#define NVOX 2097152u            // 128^3
#define PLANE 16384              // 128*128
#define CH 32                    // output z-planes per block (z-chunking)

// Scratch: ssd[t][n][c][z][y][x] in fp16  (2*2*12*128^3 halfs = 201 MB)
__device__ __half g_ssd[(size_t)2 * 2 * 12 * NVOX];
__device__ float g_msum[2] = {0.f, 0.f};   // finish_kernel re-zeroes after read
__device__ float g_loss = 0.f;

struct Acc { float4 a, b, c; };

__device__ __forceinline__ void f4zero(Acc& A) {
    A.a = make_float4(0.f,0.f,0.f,0.f);
    A.b = make_float4(0.f,0.f,0.f,0.f);
    A.c = make_float4(0.f,0.f,0.f,0.f);
}
__device__ __forceinline__ float4 f4add3(float4 p, float4 q, float4 r) {
    return make_float4(p.x+q.x+r.x, p.y+q.y+r.y, p.z+q.z+r.z, p.w+q.w+r.w);
}
__device__ __forceinline__ void f4acc(Acc& A, float4 s0, float4 s1, float4 s2) {
    A.a.x += s0.x; A.a.y += s0.y; A.a.z += s0.z; A.a.w += s0.w;
    A.b.x += s1.x; A.b.y += s1.y; A.b.z += s1.z; A.b.w += s1.w;
    A.c.x += s2.x; A.c.y += s2.y; A.c.z += s2.z; A.c.w += s2.w;
}

__device__ __forceinline__ void finalize(int zo, const Acc& A,
                                         __half* __restrict__ outBase, float& mvsum)
{
    const float k = 1.f / 27.f;
    float v0  = A.a.x*k, v1  = A.a.y*k, v2  = A.a.z*k, v3  = A.a.w*k;
    float v4  = A.b.x*k, v5  = A.b.y*k, v6  = A.b.z*k, v7  = A.b.w*k;
    float v8  = A.c.x*k, v9  = A.c.y*k, v10 = A.c.z*k, v11 = A.c.w*k;
    __half* o = outBase + (size_t)zo * PLANE;
    o[(size_t)0*NVOX]  = __float2half_rn(v0);
    o[(size_t)1*NVOX]  = __float2half_rn(v1);
    o[(size_t)2*NVOX]  = __float2half_rn(v2);
    o[(size_t)3*NVOX]  = __float2half_rn(v3);
    o[(size_t)4*NVOX]  = __float2half_rn(v4);
    o[(size_t)5*NVOX]  = __float2half_rn(v5);
    o[(size_t)6*NVOX]  = __float2half_rn(v6);
    o[(size_t)7*NVOX]  = __float2half_rn(v7);
    o[(size_t)8*NVOX]  = __float2half_rn(v8);
    o[(size_t)9*NVOX]  = __float2half_rn(v9);
    o[(size_t)10*NVOX] = __float2half_rn(v10);
    o[(size_t)11*NVOX] = __float2half_rn(v11);
    float mn = fminf(fminf(fminf(v0,v1),fminf(v2,v3)),
                     fminf(fminf(fminf(v4,v5),fminf(v6,v7)),
                           fminf(fminf(v8,v9),fminf(v10,v11))));
    float sm = ((v0+v1)+(v2+v3)) + ((v4+v5)+(v6+v7)) + ((v8+v9)+(v10+v11));
    mvsum += sm * (1.f/12.f) - mn;
}

__device__ __forceinline__ void stepC(
    int zp, int zlo, int zhi, int fz0, int fz1,
    Acc& AP, Acc& AC, Acc& AN,
    const float* __restrict__ img,
    float (*simg)[8][128], float4 (*ysb)[128][3],
    float pf[4],
    int y0, int lin, int x, int ty,
    int xm2, int xp2, int xm1, int xp1, int gy0,
    __half* __restrict__ outBase, float& mvsum)
{
    if (zp < zlo || zp > zhi) return;   // uniform per-block guard

    f4zero(AN);

    // STS plane zp+2 (prefetched into pf at previous step / preload)
    {
        const int slot = (zp + 2) % 5;
        #pragma unroll
        for (int k = 0; k < 4; ++k) {
            int e = lin + k * 256;
            int row = e >> 7, xx = e & 127;
            simg[slot][row][xx] = pf[k];
        }
    }
    // issue prefetch for plane zp+3 (clamped); consumed next step
    {
        const float* src = img + (size_t)min(zp + 3, 127) * PLANE;
        #pragma unroll
        for (int k = 0; k < 4; ++k) {
            int e = lin + k * 256;
            int row = e >> 7, xx = e & 127;
            int gy = min(max(y0 - 3 + row, 0), 127);
            pf[k] = src[gy * 128 + xx];
        }
    }
    __syncthreads();

    // y-summed diff2 for 12 channels, directly from 6 samples per dy
    const float* Pzm = &simg[(zp + 3) % 5][0][0];   // plane zp-2 (clamped)
    const float* Pzc = &simg[ zp      % 5][0][0];   // plane zp
    const float* Pzp = &simg[(zp + 2) % 5][0][0];   // plane zp+2 (clamped)

    float ys[12];
    #pragma unroll
    for (int c = 0; c < 12; ++c) ys[c] = 0.f;

    #pragma unroll
    for (int dy = -1; dy <= 1; ++dy) {
        int ly = min(max(gy0 + dy, 0), 127);
        int r  = (ly - y0 + 3) * 128;
        int rm = (max(ly - 2, 0)   - y0 + 3) * 128;
        int rp = (min(ly + 2, 127) - y0 + 3) * 128;
        float V0 = Pzm[r  + x];      // z-2
        float V1 = Pzc[r  + xm2];    // x-2
        float V2 = Pzc[rm + x];      // y-2
        float V3 = Pzc[r  + xp2];    // x+2
        float V4 = Pzp[r  + x];      // z+2
        float V5 = Pzc[rp + x];      // y+2
        float d;
        d = V1 - V0; ys[0]  += d*d;
        d = V2 - V0; ys[1]  += d*d;
        d = V2 - V1; ys[2]  += d*d;
        d = V3 - V0; ys[3]  += d*d;
        d = V3 - V2; ys[4]  += d*d;
        d = V4 - V1; ys[5]  += d*d;
        d = V4 - V2; ys[6]  += d*d;
        d = V4 - V3; ys[7]  += d*d;
        d = V5 - V0; ys[8]  += d*d;
        d = V5 - V1; ys[9]  += d*d;
        d = V5 - V3; ys[10] += d*d;
        d = V5 - V4; ys[11] += d*d;
    }
    ysb[ty][x][0] = make_float4(ys[0], ys[1], ys[2],  ys[3]);
    ysb[ty][x][1] = make_float4(ys[4], ys[5], ys[6],  ys[7]);
    ysb[ty][x][2] = make_float4(ys[8], ys[9], ys[10], ys[11]);
    __syncthreads();

    // x-sum (x edge-clamped)
    float4 s0 = f4add3(ysb[ty][xm1][0], ysb[ty][x][0], ysb[ty][xp1][0]);
    float4 s1 = f4add3(ysb[ty][xm1][1], ysb[ty][x][1], ysb[ty][xp1][1]);
    float4 s2 = f4add3(ysb[ty][xm1][2], ysb[ty][x][2], ysb[ty][xp1][2]);

    // z accumulation into zo = zp-1, zp, zp+1
    f4acc(AP, s0, s1, s2);
    f4acc(AC, s0, s1, s2);
    f4acc(AN, s0, s1, s2);
    if (zp == 0)   f4acc(AC, s0, s1, s2);   // virtual plane -1  -> zo=0
    if (zp == 127) f4acc(AC, s0, s1, s2);   // virtual plane 128 -> zo=127

    if (zp - 1 >= fz0 && zp - 1 < fz1) finalize(zp - 1, AP, outBase, mvsum);
    if (zp == 127 && fz1 == 128)       finalize(127,    AC, outBase, mvsum);
}

__global__ __launch_bounds__(256)
void ssd_kernel(const float* __restrict__ pred, const float* __restrict__ targ)
{
    const int x  = threadIdx.x;
    const int ty = threadIdx.y;
    const int y0 = blockIdx.x * 2;
    const int zc = blockIdx.y;            // z chunk
    const int tn = blockIdx.z;            // t*2+n
    const int t  = tn >> 1;
    const int n  = tn & 1;

    const int z0 = zc * CH, z1 = z0 + CH;
    const int zlo = max(z0 - 1, 0);
    const int zhi = min(z1, 127);

    const float* img = (t == 0 ? pred : targ) + (size_t)n * NVOX;
    __half* outBase = g_ssd + (size_t)tn * 12u * NVOX
                    + (size_t)(y0 + ty) * 128 + x;

    __shared__ float  simg[5][8][128];
    __shared__ float4 ysb[2][128][3];
    __shared__ float  red[256];

    const int lin = ty * 128 + x;

    // preload planes q = zlo-2 .. zlo+1 (z edge-clamped) straight into smem
    for (int q = zlo - 2; q <= zlo + 1; ++q) {
        const int slot = (q + 10) % 5;
        const float* src = img + (size_t)min(max(q, 0), 127) * PLANE;
        #pragma unroll
        for (int k = 0; k < 4; ++k) {
            int e = lin + k * 256;
            int row = e >> 7, xx = e & 127;
            int gy = min(max(y0 - 3 + row, 0), 127);
            simg[slot][row][xx] = src[gy * 128 + xx];
        }
    }
    // prefetch plane zlo+2 into registers (first step stores it)
    float pf[4];
    {
        const float* src = img + (size_t)min(zlo + 2, 127) * PLANE;
        #pragma unroll
        for (int k = 0; k < 4; ++k) {
            int e = lin + k * 256;
            int row = e >> 7, xx = e & 127;
            int gy = min(max(y0 - 3 + row, 0), 127);
            pf[k] = src[gy * 128 + xx];
        }
    }

    const int xm2 = max(x - 2, 0), xp2 = min(x + 2, 127);
    const int xm1 = max(x - 1, 0), xp1 = min(x + 1, 127);
    const int gy0 = y0 + ty;

    Acc A0, A1, A2;            // acc for zo ≡ 0,1,2 (mod 3)
    f4zero(A0); f4zero(A1); f4zero(A2);
    float mvsum = 0.f;

    const int zbase = (zlo / 3) * 3;
    for (int zb = zbase; zb <= zhi; zb += 3) {
        stepC(zb + 0, zlo, zhi, z0, z1, A2, A0, A1, img, simg, ysb, pf,
              y0, lin, x, ty, xm2, xp2, xm1, xp1, gy0, outBase, mvsum);
        stepC(zb + 1, zlo, zhi, z0, z1, A0, A1, A2, img, simg, ysb, pf,
              y0, lin, x, ty, xm2, xp2, xm1, xp1, gy0, outBase, mvsum);
        stepC(zb + 2, zlo, zhi, z0, z1, A1, A2, A0, img, simg, ysb, pf,
              y0, lin, x, ty, xm2, xp2, xm1, xp1, gy0, outBase, mvsum);
    }

    // block-reduce mind_var partial sum
    red[lin] = mvsum;
    __syncthreads();
    for (int off = 128; off > 0; off >>= 1) {
        if (lin < off) red[lin] += red[lin + off];
        __syncthreads();
    }
    if (lin == 0) atomicAdd(&g_msum[t], red[0]);
}

__global__ __launch_bounds__(256)
void loss_kernel()
{
    // each thread handles 8 voxel-pairs via 16B (8-half) loads per channel
    const unsigned i8 = blockIdx.x * 256u + threadIdx.x;   // 0 .. 2*NVOX/8-1
    const float mP = g_msum[0] * (1.f / 4194304.f);
    const float mT = g_msum[1] * (1.f / 4194304.f);

    const unsigned nn = i8 >> 18;                 // (i8*8) >> 21
    const unsigned s8 = i8 & ((NVOX / 8u) - 1u);

    const uint4* bp = (const uint4*)g_ssd + (size_t)nn       * 12u * (NVOX/8u) + s8;
    const uint4* bt = (const uint4*)g_ssd + (size_t)(2 + nn) * 12u * (NVOX/8u) + s8;

    uint4 vp[12], vt[12];
    #pragma unroll
    for (int c = 0; c < 12; ++c) vp[c] = bp[(size_t)c * (NVOX/8u)];
    #pragma unroll
    for (int c = 0; c < 12; ++c) vt[c] = bt[(size_t)c * (NVOX/8u)];

    const __half* hp = (const __half*)vp;
    const __half* ht = (const __half*)vt;

    float acc = 0.f;
    #pragma unroll
    for (int comp = 0; comp < 8; ++comp) {
        float p0 = __half2float(hp[comp]);
        float t0 = __half2float(ht[comp]);
        float mnp = p0, smp = p0;
        float mnt = t0, smt = t0;
        #pragma unroll
        for (int c = 1; c < 12; ++c) {
            float p = __half2float(hp[c * 8 + comp]);
            float q = __half2float(ht[c * 8 + comp]);
            mnp = fminf(mnp, p); smp += p;
            mnt = fminf(mnt, q); smt += q;
        }
        float mvp = smp * (1.f/12.f) - mnp;
        float mvt = smt * (1.f/12.f) - mnt;
        mvp = fminf(fmaxf(mvp, 0.001f * mP), 1000.f * mP);
        mvt = fminf(fmaxf(mvt, 0.001f * mT), 1000.f * mT);
        const float ivp = 1.f / mvp;
        const float ivt = 1.f / mvt;
        #pragma unroll
        for (int c = 0; c < 12; ++c) {
            float ep = __expf(-(__half2float(hp[c * 8 + comp]) - mnp) * ivp);
            float et = __expf(-(__half2float(ht[c * 8 + comp]) - mnt) * ivt);
            float d = ep - et;
            acc += d * d;
        }
    }

    __shared__ float red[256];
    red[threadIdx.x] = acc;
    __syncthreads();
    for (int off = 128; off > 0; off >>= 1) {
        if (threadIdx.x < off) red[threadIdx.x] += red[threadIdx.x + off];
        __syncthreads();
    }
    if (threadIdx.x == 0) atomicAdd(&g_loss, red[0]);
}

__global__ void finish_kernel(float* __restrict__ out)
{
    out[0] = g_loss * (1.f / 50331648.f);
    // reset accumulators for the next graph replay
    g_loss = 0.f; g_msum[0] = 0.f; g_msum[1] = 0.f;
}

extern "C" void kernel_launch(void* const* d_in, const int* in_sizes, int n_in,
                              void* d_out, int out_size)
{
    const float* pred = (const float*)d_in[0];
    const float* targ = (const float*)d_in[1];

    ssd_kernel<<<dim3(64, 128 / CH, 4), dim3(128, 2)>>>(pred, targ);
    loss_kernel<<<2048, 256>>>();
    finish_kernel<<<1, 1>>>((float*)d_out);
}